// round 16
// baseline (speedup 1.0000x reference)
#include <cuda_runtime.h>
#include <cuda_bf16.h>
#include <cstdint>

// Shapes: x (4,2048,2048) -> M=8192, K=2048; weight (8192,2048) -> N=8192.
#define M_TOK 8192
#define K_DIM 2048
#define N_OUT 8192
#define W_ELEMS (N_OUT * K_DIM)
#define X_ELEMS (M_TOK * K_DIM)

// GEMM tiling (bf16: BK=64 elems = 128 bytes per SMEM row)
#define BM 128
#define BN 128
#define BK 64
#define CHUNKS (K_DIM / BK)          // 32
#define STAGES 3
#define A_BYTES (BM * 128)           // 16384
#define B_BYTES (BN * 128)           // 16384
#define STAGE_BYTES (A_BYTES + B_BYTES)   // 32768
#define SMEM_TOTAL (1024 + STAGES * STAGE_BYTES)   // 99328 -> 2 CTAs/SM

// ---- device scratch ----
__device__ float g_gamma;
__device__ float g_partial[8192];         // one |w| partial per LN block
__device__ float g_eta[M_TOK];            // eta/127 per token
__device__ __nv_bfloat16 g_xb[X_ELEMS];
__device__ __nv_bfloat16 g_wb[W_ELEMS];

// ======================= helpers =======================
__device__ __forceinline__ uint32_t smem_u32(const void* p) {
    uint32_t a;
    asm("{ .reg .u64 t; cvta.to.shared.u64 t, %1; cvt.u32.u64 %0, t; }" : "=r"(a) : "l"(p));
    return a;
}
#define SW128(o) ((o) ^ (((o) >> 3) & 0x70))

__device__ __forceinline__ void cp16(uint32_t dst, const void* src) {
    asm volatile("cp.async.cg.shared.global [%0], [%1], 16;" :: "r"(dst), "l"(src));
}
#define CP_COMMIT() asm volatile("cp.async.commit_group;" ::: "memory")
#define CP_WAIT(n)  asm volatile("cp.async.wait_group %0;" :: "n"(n) : "memory")

#define LDSM4(r, a)                                                                  \
    asm volatile("ldmatrix.sync.aligned.m8n8.x4.shared.b16 {%0,%1,%2,%3}, [%4];"     \
        : "=r"((r)[0]), "=r"((r)[1]), "=r"((r)[2]), "=r"((r)[3]) : "r"(a))

#define MMAB(d, a, b0, b1)                                                           \
    asm volatile("mma.sync.aligned.m16n8k16.row.col.f32.bf16.bf16.f32 "              \
        "{%0,%1,%2,%3}, {%4,%5,%6,%7}, {%8,%9}, {%0,%1,%2,%3};"                      \
        : "+f"((d)[0]), "+f"((d)[1]), "+f"((d)[2]), "+f"((d)[3])                     \
        : "r"((a)[0]), "r"((a)[1]), "r"((a)[2]), "r"((a)[3]), "r"(b0), "r"(b1))

// ======================= prepass 1: LN + x-quant + |w| partial =======================
// Block b: LayerNorm+quant of token row b (x streamed evict-first so w stays
// L2-resident for quant_w), AND abs-sum of w[b*2048 .. +2047].  (R14 shape:
// 1 row/block, regs 30, occ ~88%, rel_err-preserving gamma partial order.)
__global__ void ln_quant_x(const float* __restrict__ x, const float* __restrict__ w) {
    int row = blockIdx.x;
    int tid = threadIdx.x;
    const float4* xr = (const float4*)(x + (size_t)row * K_DIM);
    const float4* wr = (const float4*)w + (size_t)row * 512;

    float4 p0 = __ldcs(xr + tid);            // streaming: x is read exactly once
    float4 p1 = __ldcs(xr + tid + 256);
    float4 w0 = wr[tid];                     // w re-read by quant_w: keep in L2
    float4 w1 = wr[tid + 256];
    float v[8] = {p0.x, p0.y, p0.z, p0.w, p1.x, p1.y, p1.z, p1.w};

    float s = 0.f, ss = 0.f;
    #pragma unroll
    for (int i = 0; i < 8; ++i) { s += v[i]; ss += v[i] * v[i]; }
    float wsum = fabsf(w0.x) + fabsf(w0.y) + fabsf(w0.z) + fabsf(w0.w)
               + fabsf(w1.x) + fabsf(w1.y) + fabsf(w1.z) + fabsf(w1.w);

    __shared__ float sh_s[8], sh_ss[8], sh_w[8], sh_m[8];
    #pragma unroll
    for (int o = 16; o; o >>= 1) {
        s    += __shfl_down_sync(0xFFFFFFFFu, s, o);
        ss   += __shfl_down_sync(0xFFFFFFFFu, ss, o);
        wsum += __shfl_down_sync(0xFFFFFFFFu, wsum, o);
    }
    if ((tid & 31) == 0) {
        int wi = tid >> 5;
        sh_s[wi] = s; sh_ss[wi] = ss; sh_w[wi] = wsum;
    }
    __syncthreads();
    float s_tot = 0.f, ss_tot = 0.f;
    #pragma unroll
    for (int i = 0; i < 8; ++i) { s_tot += sh_s[i]; ss_tot += sh_ss[i]; }
    if (tid == 0) {
        float wt = 0.f;
        #pragma unroll
        for (int i = 0; i < 8; ++i) wt += sh_w[i];
        g_partial[row] = wt;
    }

    float mean = s_tot * (1.0f / K_DIM);
    float var  = fmaxf(ss_tot * (1.0f / K_DIM) - mean * mean, 0.0f);
    float rstd = rsqrtf(var + 1e-5f);

    float mx = 0.f;
    #pragma unroll
    for (int i = 0; i < 8; ++i) {
        v[i] = (v[i] - mean) * rstd;
        mx = fmaxf(mx, fabsf(v[i]));
    }
    #pragma unroll
    for (int o = 16; o; o >>= 1) mx = fmaxf(mx, __shfl_down_sync(0xFFFFFFFFu, mx, o));
    if ((tid & 31) == 0) sh_m[tid >> 5] = mx;
    __syncthreads();
    float eta = 1e-5f;
    #pragma unroll
    for (int i = 0; i < 8; ++i) eta = fmaxf(eta, sh_m[i]);

    float q = 127.0f / eta;
    float b[8];
    #pragma unroll
    for (int i = 0; i < 8; ++i)
        b[i] = rintf(fminf(fmaxf(v[i] * q, -128.f), 127.f));

    __nv_bfloat162 q0 = __floats2bfloat162_rn(b[0], b[1]);
    __nv_bfloat162 q1 = __floats2bfloat162_rn(b[2], b[3]);
    __nv_bfloat162 q2 = __floats2bfloat162_rn(b[4], b[5]);
    __nv_bfloat162 q3 = __floats2bfloat162_rn(b[6], b[7]);
    uint2* xq = (uint2*)(g_xb + (size_t)row * K_DIM);
    xq[tid]       = make_uint2(*(uint32_t*)&q0, *(uint32_t*)&q1);
    xq[tid + 256] = make_uint2(*(uint32_t*)&q2, *(uint32_t*)&q3);

    if (tid == 0) g_eta[row] = eta * (1.0f / 127.0f);
}

// ======================= prepass 2: gamma reduce (folded) + w-quant =======================
// Every block (256 threads) deterministically reduces the 8192 partials to the
// SAME gamma (order matches R14: rel_err 2.07e-5), then grid-strides the ternary
// quantization with w streamed (dead after this kernel; preserves g_xb/g_wb in L2).
__global__ void quant_w(const float* __restrict__ w) {
    __shared__ float sh[8];
    __shared__ float sh_gamma;
    {
        float s = 0.f;
        #pragma unroll
        for (int j = 0; j < 32; ++j) s += g_partial[threadIdx.x + j * 256];
        #pragma unroll
        for (int o = 16; o; o >>= 1) s += __shfl_down_sync(0xFFFFFFFFu, s, o);
        if ((threadIdx.x & 31) == 0) sh[threadIdx.x >> 5] = s;
    }
    __syncthreads();
    if (threadIdx.x == 0) {
        float t = 0.f;
        #pragma unroll
        for (int i = 0; i < 8; ++i) t += sh[i];
        float gm = fmaxf(t / (float)W_ELEMS, 1e-5f);
        sh_gamma = gm;
        if (blockIdx.x == 0) g_gamma = gm;
    }
    __syncthreads();
    float inv_g = 1.0f / sh_gamma;

    const float4* w4 = (const float4*)w;
    uint2* out = (uint2*)g_wb;
    int stride = gridDim.x * blockDim.x;
    for (int i = blockIdx.x * blockDim.x + threadIdx.x; i < W_ELEMS / 4; i += stride) {
        float4 v = __ldcs(w4 + i);          // w dead after this kernel: stream it
        float b0 = rintf(fminf(fmaxf(v.x * inv_g, -1.f), 1.f));
        float b1 = rintf(fminf(fmaxf(v.y * inv_g, -1.f), 1.f));
        float b2 = rintf(fminf(fmaxf(v.z * inv_g, -1.f), 1.f));
        float b3 = rintf(fminf(fmaxf(v.w * inv_g, -1.f), 1.f));
        __nv_bfloat162 p0 = __floats2bfloat162_rn(b0, b1);
        __nv_bfloat162 p1 = __floats2bfloat162_rn(b2, b3);
        out[i] = make_uint2(*(uint32_t*)&p0, *(uint32_t*)&p1);
    }
}

// ======================= bf16 tensor-core GEMM (frozen R9/R12 config) =======================
// 256 threads = 8 warps in 2(m) x 4(n); warp tile 64x32; 2 CTAs per SM.
__global__ void __launch_bounds__(256, 2) gemm_hmma(float* __restrict__ out) {
    extern __shared__ char smem[];
    uint32_t sb = (smem_u32(smem) + 1023u) & ~1023u;

    const int tid  = threadIdx.x;
    const int lane = tid & 31;
    const int wid  = tid >> 5;
    const int wm   = wid >> 2;        // 0..1 (64 rows each)
    const int wn   = wid & 3;         // 0..3 (32 cols each)
    const int bx   = blockIdx.x;
    const int by   = blockIdx.y;

    const char* asrc0 = (const char*)(g_xb + (size_t)(by * BM) * K_DIM);
    const char* bsrc0 = (const char*)(g_wb + (size_t)(bx * BN) * K_DIM);

    const int lrow = lane & 15;
    const int lhi  = (lane & 16);

    float acc[4][4][4];
    #pragma unroll
    for (int mf = 0; mf < 4; ++mf)
        #pragma unroll
        for (int nf = 0; nf < 4; ++nf)
            #pragma unroll
            for (int r = 0; r < 4; ++r) acc[mf][nf][r] = 0.f;

    auto load_stage = [&](int s, int chunk) {
        uint32_t abase = sb + s * STAGE_BYTES;
        uint32_t bbase = abase + A_BYTES;
        const char* asrc = asrc0 + chunk * (BK * 2);
        const char* bsrc = bsrc0 + chunk * (BK * 2);
        #pragma unroll
        for (int j = 0; j < 8; ++j) {
            int t = tid + j * 256;
            if (t < 1024) {
                int row = t >> 3, seg = t & 7;
                cp16(abase + SW128(row * 128 + seg * 16),
                     asrc + (size_t)row * (K_DIM * 2) + seg * 16);
            } else {
                int u = t - 1024;
                int row = u >> 3, seg = u & 7;
                cp16(bbase + SW128(row * 128 + seg * 16),
                     bsrc + (size_t)row * (K_DIM * 2) + seg * 16);
            }
        }
    };

    load_stage(0, 0);
    CP_COMMIT();
    load_stage(1, 1);
    CP_COMMIT();

    const int arow0 = wm * 64 + lrow;          // + mf*16
    const int brow0 = wn * 32 + lrow;          // + nf2*16

    #pragma unroll 1
    for (int i = 0; i < CHUNKS; ++i) {
        CP_WAIT(1);
        __syncthreads();

        if (i + 2 < CHUNKS)
            load_stage((i + 2) % STAGES, i + 2);
        CP_COMMIT();

        uint32_t abase = sb + (i % STAGES) * STAGE_BYTES;
        uint32_t bbase = abase + A_BYTES;

        #pragma unroll
        for (int ks = 0; ks < 4; ++ks) {
            uint32_t a[4][4], b[2][4];
            #pragma unroll
            for (int mf = 0; mf < 4; ++mf)
                LDSM4(a[mf], abase + SW128((arow0 + mf * 16) * 128 + ks * 32 + lhi));
            #pragma unroll
            for (int nf2 = 0; nf2 < 2; ++nf2)
                LDSM4(b[nf2], bbase + SW128((brow0 + nf2 * 16) * 128 + ks * 32 + lhi));
            #pragma unroll
            for (int mf = 0; mf < 4; ++mf)
                #pragma unroll
                for (int nf2 = 0; nf2 < 2; ++nf2) {
                    MMAB(acc[mf][2 * nf2],     a[mf], b[nf2][0], b[nf2][2]);
                    MMAB(acc[mf][2 * nf2 + 1], a[mf], b[nf2][1], b[nf2][3]);
                }
        }
    }

    // ---- epilogue: scale by gamma * eta/127, write float2 ----
    const float gamma = g_gamma;
    const int row0 = by * BM + wm * 64;
    const int col0 = bx * BN + wn * 32;
    const int rq = lane >> 2;
    const int cq = (lane & 3) * 2;
    #pragma unroll
    for (int mf = 0; mf < 4; ++mf) {
        int r = row0 + mf * 16 + rq;
        float s0 = gamma * g_eta[r];
        float s1 = gamma * g_eta[r + 8];
        float* p0 = out + (size_t)r * N_OUT + col0 + cq;
        float* p1 = out + (size_t)(r + 8) * N_OUT + col0 + cq;
        #pragma unroll
        for (int nf = 0; nf < 4; ++nf) {
            float2 o0 = make_float2(acc[mf][nf][0] * s0, acc[mf][nf][1] * s0);
            float2 o1 = make_float2(acc[mf][nf][2] * s1, acc[mf][nf][3] * s1);
            *(float2*)(p0 + nf * 8) = o0;
            *(float2*)(p1 + nf * 8) = o1;
        }
    }
}

// ======================= launch (3 kernels) =======================
extern "C" void kernel_launch(void* const* d_in, const int* in_sizes, int n_in,
                              void* d_out, int out_size) {
    const float* x = (const float*)d_in[0];
    const float* w = (const float*)d_in[1];
    float* out = (float*)d_out;

    cudaFuncSetAttribute(gemm_hmma, cudaFuncAttributeMaxDynamicSharedMemorySize, SMEM_TOTAL);

    ln_quant_x<<<M_TOK, 256>>>(x, w);    // LN + x-quant + |w| partials (x streamed)
    quant_w<<<2048, 256>>>(w);           // gamma reduce (folded) + w-quant (streamed)
    gemm_hmma<<<dim3(N_OUT / BN, M_TOK / BM), 256, SMEM_TOTAL>>>(out);
}